// round 1
// baseline (speedup 1.0000x reference)
#include <cuda_runtime.h>
#include <cstddef>

// Problem constants
#define NTOT 12000
#define TT   6000
#define HH   4000
#define DD   256
#define NH   8
#define HD   32
#define EV   64
#define LOG2E 1.4426950408889634f

// Scratch (device globals -- no allocation allowed)
__device__ float g_Q[(size_t)TT * DD];   // projected+scaled queries (log2 domain)
__device__ float g_K[(size_t)HH * DD];   // projected keys
__device__ float g_V[(size_t)HH * DD];   // projected values
__device__ float g_A[(size_t)NTOT * DD]; // assembled attn_all

typedef unsigned long long u64;

// ---------- packed f32x2 helpers (ptxas never auto-fuses these) ----------
__device__ __forceinline__ u64 pk2(float a, float b) {
    u64 r; asm("mov.b64 %0, {%1, %2};" : "=l"(r) : "f"(a), "f"(b)); return r;
}
__device__ __forceinline__ float2 upk2(u64 v) {
    float2 r; asm("mov.b64 {%0, %1}, %2;" : "=f"(r.x), "=f"(r.y) : "l"(v)); return r;
}
__device__ __forceinline__ u64 fma2(u64 a, u64 b, u64 c) {
    u64 d; asm("fma.rn.f32x2 %0, %1, %2, %3;" : "=l"(d) : "l"(a), "l"(b), "l"(c)); return d;
}
__device__ __forceinline__ u64 mul2(u64 a, u64 b) {
    u64 d; asm("mul.rn.f32x2 %0, %1, %2;" : "=l"(d) : "l"(a), "l"(b)); return d;
}
__device__ __forceinline__ u64 add2(u64 a, u64 b) {
    u64 d; asm("add.rn.f32x2 %0, %1, %2;" : "=l"(d) : "l"(a), "l"(b)); return d;
}
__device__ __forceinline__ float ex2f(float x) {
    float r; asm("ex2.approx.ftz.f32 %0, %1;" : "=f"(r) : "f"(x)); return r;
}

// ---------------------------------------------------------------------------
// Unified GEMM: Y[m, 0:256] = (X[src(m), :] @ W^T + bias) * scale
//   src(m) = idx ? idx[m] : m.   W is [256,256] row-major, out_j = sum_k X_k W[j,k]
// Tile 64x64, k-tile 16, 256 threads, 4x4 micro-tile with f32x2 over columns.
// ---------------------------------------------------------------------------
__global__ void __launch_bounds__(256) gemm_kernel(
    const float* __restrict__ X, const int* __restrict__ idx,
    const float* __restrict__ W, const float* __restrict__ bias,
    float* __restrict__ Y, int M, float scale)
{
    __shared__ __align__(16) float Xs[16][64];
    __shared__ __align__(16) float Ws[16][64];

    const int tx = threadIdx.x & 15;     // 0..15 -> output cols (x4)
    const int ty = threadIdx.x >> 4;     // 0..15 -> output rows (x4)
    const int m0 = blockIdx.y * 64;
    const int n0 = blockIdx.x * 64;

    u64 c2[4][2];
#pragma unroll
    for (int i = 0; i < 4; i++) { c2[i][0] = 0ull; c2[i][1] = 0ull; }

    const int lr = threadIdx.x >> 2;        // 0..63 (tile row to load)
    const int lc = (threadIdx.x & 3) * 4;   // 0,4,8,12 (k offset)
    int xrow = m0 + lr; if (xrow >= M) xrow = M - 1;   // clamp; store guarded
    if (idx) xrow = idx[xrow];
    const float* Xrow = X + (size_t)xrow * DD;
    const float* Wrow = W + (size_t)(n0 + lr) * DD;

    for (int k0 = 0; k0 < DD; k0 += 16) {
        __syncthreads();
        float4 xv = *(const float4*)(Xrow + k0 + lc);
        Xs[lc + 0][lr] = xv.x; Xs[lc + 1][lr] = xv.y;
        Xs[lc + 2][lr] = xv.z; Xs[lc + 3][lr] = xv.w;
        float4 wv = *(const float4*)(Wrow + k0 + lc);
        Ws[lc + 0][lr] = wv.x; Ws[lc + 1][lr] = wv.y;
        Ws[lc + 2][lr] = wv.z; Ws[lc + 3][lr] = wv.w;
        __syncthreads();
#pragma unroll
        for (int kk = 0; kk < 16; kk++) {
            const u64* wb = (const u64*)&Ws[kk][tx * 4];
            u64 b0 = wb[0], b1 = wb[1];
#pragma unroll
            for (int i = 0; i < 4; i++) {
                float a = Xs[kk][ty * 4 + i];
                u64 a2 = pk2(a, a);
                c2[i][0] = fma2(a2, b0, c2[i][0]);
                c2[i][1] = fma2(a2, b1, c2[i][1]);
            }
        }
    }

    const float bc0 = bias[n0 + tx * 4 + 0];
    const float bc1 = bias[n0 + tx * 4 + 1];
    const float bc2 = bias[n0 + tx * 4 + 2];
    const float bc3 = bias[n0 + tx * 4 + 3];
#pragma unroll
    for (int i = 0; i < 4; i++) {
        int m = m0 + ty * 4 + i;
        if (m < M) {
            float2 v0 = upk2(c2[i][0]);
            float2 v1 = upk2(c2[i][1]);
            float* yr = Y + (size_t)m * DD + n0 + tx * 4;
            yr[0] = (v0.x + bc0) * scale;
            yr[1] = (v0.y + bc1) * scale;
            yr[2] = (v1.x + bc2) * scale;
            yr[3] = (v1.y + bc3) * scale;
        }
    }
}

// ---------------------------------------------------------------------------
// Fused flash attention over the bipartite graph.
// Block = 128 threads = 8 heads x 16 tail rows; one (h,t) pair per thread.
// Streams keys/values in 16-row chunks through shared memory.
// Scores computed in log2 domain (scaling*log2e folded into g_Q, log2e folded
// into the edge table). Masked entries get sentinel -30000 -> weight 0.
// ---------------------------------------------------------------------------
#define MASKED_SC (-30000.0f)
#define M_INIT    (-10000.0f)

__global__ void __launch_bounds__(128, 3) attn_kernel(
    const int* __restrict__ adj, const int* __restrict__ cidx,
    const int* __restrict__ gtail, const float* __restrict__ edge_emb)
{
    __shared__ __align__(16) float Ks[16 * DD];
    __shared__ __align__(16) float Vs[16 * DD];
    __shared__ int   codeS[16][17];     // padded: bank-conflict-free over t
    __shared__ float edge_sh[EV * NH];  // pre-scaled by log2e

    const int tid = threadIdx.x;
    const int h   = tid >> 4;   // 0..7
    const int tl  = tid & 15;   // 0..15
    const int t0  = blockIdx.x * 16;

    for (int i = tid; i < EV * NH; i += 128)
        edge_sh[i] = edge_emb[i] * LOG2E;

    // q row (32 floats) into packed-pair registers
    u64 q2[16];
    {
        const ulonglong2* qr =
            (const ulonglong2*)(g_Q + (size_t)(t0 + tl) * DD + h * HD);
#pragma unroll
        for (int i = 0; i < 8; i++) { ulonglong2 v = qr[i]; q2[2*i] = v.x; q2[2*i+1] = v.y; }
    }
    u64 o2[16];
#pragma unroll
    for (int i = 0; i < 16; i++) o2[i] = 0ull;
    float m = M_INIT, l = 0.0f;

    for (int s0 = 0; s0 < HH; s0 += 16) {
        __syncthreads();
        {
            const float4* Kg = (const float4*)(g_K + (size_t)s0 * DD);
            const float4* Vg = (const float4*)(g_V + (size_t)s0 * DD);
            float4* Ksv = (float4*)Ks;
            float4* Vsv = (float4*)Vs;
#pragma unroll
            for (int i = 0; i < 8; i++) {          // 16*256/4 = 1024 float4
                Ksv[tid + i * 128] = Kg[tid + i * 128];
                Vsv[tid + i * 128] = Vg[tid + i * 128];
            }
#pragma unroll
            for (int i = 0; i < 2; i++) {          // 16x16 code tile
                int e  = tid + i * 128;
                int rt = e >> 4, rs = e & 15;
                size_t off = (size_t)(t0 + rt) * HH + s0 + rs;
                int a = adj[off];
                int c = cidx[off];
                codeS[rt][rs] = a ? c : -1;
            }
        }
        __syncthreads();

        float sc[16];
#pragma unroll
        for (int s = 0; s < 16; s++) {
            const ulonglong2* kr = (const ulonglong2*)(Ks + s * DD + h * HD);
            u64 acc0 = 0ull, acc1 = 0ull;
#pragma unroll
            for (int i = 0; i < 4; i++) {
                ulonglong2 ka = kr[2 * i];
                ulonglong2 kb = kr[2 * i + 1];
                acc0 = fma2(q2[4 * i + 0], ka.x, acc0);
                acc1 = fma2(q2[4 * i + 1], ka.y, acc1);
                acc0 = fma2(q2[4 * i + 2], kb.x, acc0);
                acc1 = fma2(q2[4 * i + 3], kb.y, acc1);
            }
            float2 av = upk2(add2(acc0, acc1));
            float sv = av.x + av.y;
            int code = codeS[tl][s];
            sc[s] = (code >= 0) ? (sv + edge_sh[code * NH + h]) : MASKED_SC;
        }

        float mc = sc[0];
#pragma unroll
        for (int s = 1; s < 16; s++) mc = fmaxf(mc, sc[s]);
        float mn = fmaxf(m, mc);
        float rescale = ex2f(m - mn);
        m = mn;
        l *= rescale;
        u64 r2 = pk2(rescale, rescale);
#pragma unroll
        for (int i = 0; i < 16; i++) o2[i] = mul2(o2[i], r2);

#pragma unroll
        for (int s = 0; s < 16; s++) {
            float p = ex2f(sc[s] - mn);   // masked: arg <= -20000 -> 0
            l += p;
            u64 p2 = pk2(p, p);
            const ulonglong2* vr = (const ulonglong2*)(Vs + s * DD + h * HD);
#pragma unroll
            for (int i = 0; i < 8; i++) {
                ulonglong2 vv = vr[i];
                o2[2 * i]     = fma2(p2, vv.x, o2[2 * i]);
                o2[2 * i + 1] = fma2(p2, vv.y, o2[2 * i + 1]);
            }
        }
    }

    float inv = 1.0f / l;
    int trow = gtail[t0 + tl];
    float* dst = g_A + (size_t)trow * DD + h * HD;
#pragma unroll
    for (int i = 0; i < 16; i++) {
        float2 v = upk2(o2[i]);
        dst[2 * i]     = v.x * inv;
        dst[2 * i + 1] = v.y * inv;
    }
}

// ---------------------------------------------------------------------------
__global__ void zero_A_kernel()
{
    int i = blockIdx.x * 256 + threadIdx.x;
    if (i < NTOT * DD / 4)
        ((float4*)g_A)[i] = make_float4(0.f, 0.f, 0.f, 0.f);
}

__global__ void copy_head_kernel(const float* __restrict__ query,
                                 const int* __restrict__ ghead)
{
    int i = blockIdx.x * 256 + threadIdx.x;
    if (i < HH * DD / 4) {
        int row = i >> 6;
        int c4  = i & 63;
        int r = ghead[row];
        ((float4*)(g_A + (size_t)r * DD))[c4] =
            ((const float4*)(query + (size_t)r * DD))[c4];
    }
}

// ---------------------------------------------------------------------------
extern "C" void kernel_launch(void* const* d_in, const int* in_sizes, int n_in,
                              void* d_out, int out_size)
{
    const float* query = (const float*)d_in[0];
    const float* key   = (const float*)d_in[1];
    const float* value = (const float*)d_in[2];
    const int*   adj   = (const int*)d_in[3];
    const int*   cidx  = (const int*)d_in[4];
    const int*   gtail = (const int*)d_in[5];
    const int*   ghead = (const int*)d_in[6];
    const float* Wq = (const float*)d_in[7];
    const float* bq = (const float*)d_in[8];
    const float* Wk = (const float*)d_in[9];
    const float* bk = (const float*)d_in[10];
    const float* Wv = (const float*)d_in[11];
    const float* bv = (const float*)d_in[12];
    const float* Wo = (const float*)d_in[13];
    const float* bo = (const float*)d_in[14];
    const float* edge = (const float*)d_in[15];
    float* out = (float*)d_out;

    float *pQ, *pK, *pV, *pA;
    cudaGetSymbolAddress((void**)&pQ, g_Q);
    cudaGetSymbolAddress((void**)&pK, g_K);
    cudaGetSymbolAddress((void**)&pV, g_V);
    cudaGetSymbolAddress((void**)&pA, g_A);

    // fold softmax scaling and log2(e) into Q; edge table scaled in-kernel
    const float SCALE_Q = 0.17677669529663687f * LOG2E;  // 32^-0.5 * log2(e)

    zero_A_kernel<<<(NTOT * DD / 4 + 255) / 256, 256>>>();

    dim3 gq(4, (TT + 63) / 64);
    gemm_kernel<<<gq, 256>>>(query, gtail, Wq, bq, pQ, TT, SCALE_Q);
    dim3 gk(4, (HH + 63) / 64);
    gemm_kernel<<<gk, 256>>>(key,   ghead, Wk, bk, pK, HH, 1.0f);
    gemm_kernel<<<gk, 256>>>(value, ghead, Wv, bv, pV, HH, 1.0f);

    copy_head_kernel<<<(HH * DD / 4 + 255) / 256, 256>>>(query, ghead);

    attn_kernel<<<TT / 16, 128>>>(adj, cidx, gtail, edge);

    dim3 go(4, (NTOT + 63) / 64);
    gemm_kernel<<<go, 256>>>(pA, nullptr, Wo, bo, out, NTOT, 1.0f);
}

// round 4
// speedup vs baseline: 2.6346x; 2.6346x over previous
#include <cuda_runtime.h>
#include <cuda_fp16.h>
#include <cstdint>
#include <cstddef>

// Problem constants
#define NTOT 12000
#define TT   6000
#define HH   4000
#define DD   256
#define NH   8
#define HD   32
#define EV   64
#define LOG2E 1.4426950408889634f

// Scratch (device globals -- no allocation allowed)
__device__ __half g_Qh[(size_t)TT * DD];    // projected+scaled queries (log2 domain), fp16
__device__ __half g_Kh[(size_t)HH * DD];    // projected keys, fp16
__device__ float  g_V [(size_t)HH * DD];    // projected values, f32
__device__ __half g_Vth[(size_t)DD * HH];   // transposed values [dim][key], fp16
__device__ float  g_A [(size_t)NTOT * DD];  // assembled attn_all

typedef unsigned long long u64;
typedef unsigned int u32;

// ---------- packed f32x2 helpers ----------
__device__ __forceinline__ u64 pk2(float a, float b) {
    u64 r; asm("mov.b64 %0, {%1, %2};" : "=l"(r) : "f"(a), "f"(b)); return r;
}
__device__ __forceinline__ float2 upk2(u64 v) {
    float2 r; asm("mov.b64 {%0, %1}, %2;" : "=f"(r.x), "=f"(r.y) : "l"(v)); return r;
}
__device__ __forceinline__ u64 fma2(u64 a, u64 b, u64 c) {
    u64 d; asm("fma.rn.f32x2 %0, %1, %2, %3;" : "=l"(d) : "l"(a), "l"(b), "l"(c)); return d;
}
__device__ __forceinline__ float ex2f(float x) {
    float r; asm("ex2.approx.ftz.f32 %0, %1;" : "=f"(r) : "f"(x)); return r;
}
__device__ __forceinline__ u32 packh2(float lo, float hi) {
    u32 r; asm("cvt.rn.f16x2.f32 %0, %1, %2;" : "=r"(r) : "f"(hi), "f"(lo)); return r;
}
__device__ __forceinline__ u32 smem_u32(const void* p) {
    u32 a; asm("{ .reg .u64 t; cvta.to.shared.u64 t, %1; cvt.u32.u64 %0, t; }" : "=r"(a) : "l"(p));
    return a;
}
__device__ __forceinline__ void cp16(void* dst, const void* src) {
    asm volatile("cp.async.cg.shared.global [%0], [%1], 16;"
                 :: "r"(smem_u32(dst)), "l"(src) : "memory");
}
#define CP_COMMIT() asm volatile("cp.async.commit_group;" ::: "memory")
#define CP_WAIT1()  asm volatile("cp.async.wait_group 1;" ::: "memory")
#define CP_WAIT0()  asm volatile("cp.async.wait_group 0;" ::: "memory")

// mma.sync m16n8k16 f16 x f16 -> f32   (sm_80-class; safe on this toolchain)
__device__ __forceinline__ void mma_f16(float* d, const u32* a, u32 b0, u32 b1) {
    asm volatile(
        "mma.sync.aligned.m16n8k16.row.col.f32.f16.f16.f32 "
        "{%0,%1,%2,%3}, {%4,%5,%6,%7}, {%8,%9}, {%0,%1,%2,%3};"
        : "+f"(d[0]), "+f"(d[1]), "+f"(d[2]), "+f"(d[3])
        : "r"(a[0]), "r"(a[1]), "r"(a[2]), "r"(a[3]), "r"(b0), "r"(b1));
}

// ---------------------------------------------------------------------------
// Unified GEMM: Y[m, :] = (X[src(m), :] @ W^T + bias) * scale
// Optional fp16 output (Yh != null).
// ---------------------------------------------------------------------------
__global__ void __launch_bounds__(256) gemm_kernel(
    const float* __restrict__ X, const int* __restrict__ idx,
    const float* __restrict__ W, const float* __restrict__ bias,
    float* __restrict__ Y, __half* __restrict__ Yh, int M, float scale)
{
    __shared__ __align__(16) float Xs[16][64];
    __shared__ __align__(16) float Ws[16][64];

    const int tx = threadIdx.x & 15;
    const int ty = threadIdx.x >> 4;
    const int m0 = blockIdx.y * 64;
    const int n0 = blockIdx.x * 64;

    u64 c2[4][2];
#pragma unroll
    for (int i = 0; i < 4; i++) { c2[i][0] = 0ull; c2[i][1] = 0ull; }

    const int lr = threadIdx.x >> 2;
    const int lc = (threadIdx.x & 3) * 4;
    int xrow = m0 + lr; if (xrow >= M) xrow = M - 1;
    if (idx) xrow = idx[xrow];
    const float* Xrow = X + (size_t)xrow * DD;
    const float* Wrow = W + (size_t)(n0 + lr) * DD;

    for (int k0 = 0; k0 < DD; k0 += 16) {
        __syncthreads();
        float4 xv = *(const float4*)(Xrow + k0 + lc);
        Xs[lc + 0][lr] = xv.x; Xs[lc + 1][lr] = xv.y;
        Xs[lc + 2][lr] = xv.z; Xs[lc + 3][lr] = xv.w;
        float4 wv = *(const float4*)(Wrow + k0 + lc);
        Ws[lc + 0][lr] = wv.x; Ws[lc + 1][lr] = wv.y;
        Ws[lc + 2][lr] = wv.z; Ws[lc + 3][lr] = wv.w;
        __syncthreads();
#pragma unroll
        for (int kk = 0; kk < 16; kk++) {
            const u64* wb = (const u64*)&Ws[kk][tx * 4];
            u64 b0 = wb[0], b1 = wb[1];
#pragma unroll
            for (int i = 0; i < 4; i++) {
                float a = Xs[kk][ty * 4 + i];
                u64 a2 = pk2(a, a);
                c2[i][0] = fma2(a2, b0, c2[i][0]);
                c2[i][1] = fma2(a2, b1, c2[i][1]);
            }
        }
    }

    const float bc0 = bias[n0 + tx * 4 + 0];
    const float bc1 = bias[n0 + tx * 4 + 1];
    const float bc2 = bias[n0 + tx * 4 + 2];
    const float bc3 = bias[n0 + tx * 4 + 3];
#pragma unroll
    for (int i = 0; i < 4; i++) {
        int m = m0 + ty * 4 + i;
        if (m < M) {
            float2 v0 = upk2(c2[i][0]);
            float2 v1 = upk2(c2[i][1]);
            float r0 = (v0.x + bc0) * scale;
            float r1 = (v0.y + bc1) * scale;
            float r2 = (v1.x + bc2) * scale;
            float r3 = (v1.y + bc3) * scale;
            if (Yh) {
                __half* yr = Yh + (size_t)m * DD + n0 + tx * 4;
                yr[0] = __float2half_rn(r0); yr[1] = __float2half_rn(r1);
                yr[2] = __float2half_rn(r2); yr[3] = __float2half_rn(r3);
            } else {
                float* yr = Y + (size_t)m * DD + n0 + tx * 4;
                yr[0] = r0; yr[1] = r1; yr[2] = r2; yr[3] = r3;
            }
        }
    }
}

// ---------------------------------------------------------------------------
// V transpose + fp16 convert: g_V[4000][256] f32 -> g_Vth[256][4000] half
// ---------------------------------------------------------------------------
__global__ void __launch_bounds__(256) transpose_v_kernel()
{
    __shared__ float t[32][33];
    int s0 = blockIdx.x * 32, d0 = blockIdx.y * 32;
    int x = threadIdx.x & 31, y = threadIdx.x >> 5;   // 32x8
#pragma unroll
    for (int i = 0; i < 32; i += 8)
        t[y + i][x] = g_V[(size_t)(s0 + y + i) * DD + d0 + x];
    __syncthreads();
#pragma unroll
    for (int i = 0; i < 32; i += 8)
        g_Vth[(size_t)(d0 + y + i) * HH + s0 + x] = __float2half_rn(t[x][y + i]);
}

// ---------------------------------------------------------------------------
// mma.sync fp16 flash attention.
// Block = 128 threads = 4 warps = 4 heads; 32 tails/block.
// Grid (188, 2): x = tail tile, y = head group (heads hg*4 .. hg*4+3).
// Chunk = 16 keys = one k16 for PV. 250 chunks, cp.async double-buffered.
// ---------------------------------------------------------------------------
#define NCH 250

struct SmemT {
    __half Ks [2][16][136];   // [buf][key][dim(4 heads*32), row 272B: banks 4g+t]
    __half Vts[2][128][24];   // [buf][dim][key16, row 48B: banks 12g+t]
    int    adjS[2][32][20];   // [buf][tail][key16], 80B rows (16B-aligned cp dst)
    int    cidS[2][32][20];
    float  edge[4][64];       // per-warp-head edge bias table (log2-scaled)
};

__device__ __forceinline__ void stage_tiles(SmemT* s, int b, int it,
    const int* __restrict__ adj, const int* __restrict__ cidx,
    int tid, int t0, int hg)
{
    const int s0 = it * 16;
    {   // K tile: 16 rows x 256B
        int e = tid * 2;
#pragma unroll
        for (int i = 0; i < 2; i++, e++) {
            int r = e >> 4, seg = e & 15;
            cp16(&s->Ks[b][r][seg * 8],
                 g_Kh + ((size_t)(s0 + r) * DD + hg * 128 + seg * 8));
        }
    }
    {   // Vt tile: 128 rows x 32B
        int e = tid * 2;
#pragma unroll
        for (int i = 0; i < 2; i++, e++) {
            int r = e >> 1, seg = e & 1;
            cp16(&s->Vts[b][r][seg * 8],
                 g_Vth + ((size_t)(hg * 128 + r) * HH + s0 + seg * 8));
        }
    }
    {   // adj / cidx tiles: 32 rows x 64B each
        int r = tid >> 2, seg = tid & 3;
        int tr = t0 + r; if (tr > TT - 1) tr = TT - 1;
        cp16(&s->adjS[b][r][seg * 4], adj  + (size_t)tr * HH + s0 + seg * 4);
        cp16(&s->cidS[b][r][seg * 4], cidx + (size_t)tr * HH + s0 + seg * 4);
    }
}

__global__ void __launch_bounds__(128, 3) attn_mma_kernel(
    const int* __restrict__ adj, const int* __restrict__ cidx,
    const int* __restrict__ gtail, const float* __restrict__ edge_emb)
{
    __shared__ SmemT sm;

    const int tid = threadIdx.x;
    const int w   = tid >> 5;          // warp = head within group
    const int lane = tid & 31;
    const int g   = lane >> 2;         // group id (row within fragment)
    const int tq  = lane & 3;          // thread-in-group (col pair)
    const int hg  = blockIdx.y;
    const int hh  = hg * 4 + w;        // global head
    const int t0  = blockIdx.x * 32;

    // edge table: edge[w][c] = edge_emb[c][head] * log2(e)
    for (int i = tid; i < 4 * EV; i += 128) {
        int ww = i >> 6, c = i & 63;
        sm.edge[ww][c] = edge_emb[c * NH + hg * 4 + ww] * LOG2E;
    }

    // Q A-fragments (persist whole kernel): Qa[mtile][ktile][4]
    u32 Qa[2][2][4];
#pragma unroll
    for (int m = 0; m < 2; m++) {
        int r0 = t0 + m * 16 + g;      if (r0 > TT - 1) r0 = TT - 1;
        int r1 = t0 + m * 16 + g + 8;  if (r1 > TT - 1) r1 = TT - 1;
#pragma unroll
        for (int kt = 0; kt < 2; kt++) {
            int db = hh * HD + kt * 16 + 2 * tq;
            Qa[m][kt][0] = *(const u32*)(g_Qh + (size_t)r0 * DD + db);
            Qa[m][kt][1] = *(const u32*)(g_Qh + (size_t)r1 * DD + db);
            Qa[m][kt][2] = *(const u32*)(g_Qh + (size_t)r0 * DD + db + 8);
            Qa[m][kt][3] = *(const u32*)(g_Qh + (size_t)r1 * DD + db + 8);
        }
    }

    float O[2][4][4];
#pragma unroll
    for (int m = 0; m < 2; m++)
#pragma unroll
        for (int n = 0; n < 4; n++)
#pragma unroll
            for (int j = 0; j < 4; j++) O[m][n][j] = 0.f;
    float l[2][2] = {{0.f, 0.f}, {0.f, 0.f}};

    stage_tiles(&sm, 0, 0, adj, cidx, tid, t0, hg);
    CP_COMMIT();

    for (int it = 0; it < NCH; it++) {
        const int buf = it & 1;
        if (it + 1 < NCH) {
            stage_tiles(&sm, buf ^ 1, it + 1, adj, cidx, tid, t0, hg);
            CP_COMMIT();
            CP_WAIT1();
        } else {
            CP_WAIT0();
        }
        __syncthreads();

        // ---- QK: S[m][nt] += Q[m] . K^T ----
        float S[2][2][4];
#pragma unroll
        for (int m = 0; m < 2; m++)
#pragma unroll
            for (int nt = 0; nt < 2; nt++)
#pragma unroll
                for (int j = 0; j < 4; j++) S[m][nt][j] = 0.f;

#pragma unroll
        for (int nt = 0; nt < 2; nt++) {
#pragma unroll
            for (int kt = 0; kt < 2; kt++) {
                const __half* kp = &sm.Ks[buf][nt * 8 + g][w * HD + kt * 16 + 2 * tq];
                u32 b0 = *(const u32*)kp;
                u32 b1 = *(const u32*)(kp + 8);
#pragma unroll
                for (int m = 0; m < 2; m++)
                    mma_f16(S[m][nt], Qa[m][kt], b0, b1);
            }
        }

        // ---- softmax (fixed-reference, log2 domain) + pack to A frags ----
        u32 Pa[2][4];
#pragma unroll
        for (int m = 0; m < 2; m++) {
#pragma unroll
            for (int nt = 0; nt < 2; nt++) {
                int colb = nt * 8 + 2 * tq;
                int r0 = m * 16 + g, r1 = r0 + 8;
                int2 a0 = *(const int2*)&sm.adjS[buf][r0][colb];
                int2 a1 = *(const int2*)&sm.adjS[buf][r1][colb];
                int2 c0 = *(const int2*)&sm.cidS[buf][r0][colb];
                int2 c1 = *(const int2*)&sm.cidS[buf][r1][colb];
                float p00 = a0.x ? ex2f(S[m][nt][0] + sm.edge[w][c0.x]) : 0.f;
                float p01 = a0.y ? ex2f(S[m][nt][1] + sm.edge[w][c0.y]) : 0.f;
                float p10 = a1.x ? ex2f(S[m][nt][2] + sm.edge[w][c1.x]) : 0.f;
                float p11 = a1.y ? ex2f(S[m][nt][3] + sm.edge[w][c1.y]) : 0.f;
                S[m][nt][0] = p00; S[m][nt][1] = p01;
                S[m][nt][2] = p10; S[m][nt][3] = p11;
                l[m][0] += p00 + p01;
                l[m][1] += p10 + p11;
            }
            Pa[m][0] = packh2(S[m][0][0], S[m][0][1]);
            Pa[m][1] = packh2(S[m][0][2], S[m][0][3]);
            Pa[m][2] = packh2(S[m][1][0], S[m][1][1]);
            Pa[m][3] = packh2(S[m][1][2], S[m][1][3]);
        }

        // ---- PV: O[m][nd] += P[m] . V ----
#pragma unroll
        for (int nd = 0; nd < 4; nd++) {
            const __half* vp = &sm.Vts[buf][w * HD + nd * 8 + g][2 * tq];
            u32 b0 = *(const u32*)vp;
            u32 b1 = *(const u32*)(vp + 8);
#pragma unroll
            for (int m = 0; m < 2; m++)
                mma_f16(O[m][nd], Pa[m], b0, b1);
        }
        __syncthreads();
    }

    // quad-reduce l (cols live across the 4 lanes of each group)
#pragma unroll
    for (int m = 0; m < 2; m++)
#pragma unroll
        for (int j = 0; j < 2; j++) {
            float v = l[m][j];
            v += __shfl_xor_sync(0xffffffffu, v, 1);
            v += __shfl_xor_sync(0xffffffffu, v, 2);
            l[m][j] = v;
        }

#pragma unroll
    for (int m = 0; m < 2; m++) {
        int tg0 = t0 + m * 16 + g;
        int tg1 = tg0 + 8;
        float inv0 = 1.0f / l[m][0];
        float inv1 = 1.0f / l[m][1];
        if (tg0 < TT) {
            float* dst = g_A + (size_t)gtail[tg0] * DD + hh * HD;
#pragma unroll
            for (int nd = 0; nd < 4; nd++) {
                float2 v; v.x = O[m][nd][0] * inv0; v.y = O[m][nd][1] * inv0;
                *(float2*)(dst + nd * 8 + 2 * tq) = v;
            }
        }
        if (tg1 < TT) {
            float* dst = g_A + (size_t)gtail[tg1] * DD + hh * HD;
#pragma unroll
            for (int nd = 0; nd < 4; nd++) {
                float2 v; v.x = O[m][nd][2] * inv1; v.y = O[m][nd][3] * inv1;
                *(float2*)(dst + nd * 8 + 2 * tq) = v;
            }
        }
    }
}

// ---------------------------------------------------------------------------
__global__ void zero_A_kernel()
{
    int i = blockIdx.x * 256 + threadIdx.x;
    if (i < NTOT * DD / 4)
        ((float4*)g_A)[i] = make_float4(0.f, 0.f, 0.f, 0.f);
}

__global__ void copy_head_kernel(const float* __restrict__ query,
                                 const int* __restrict__ ghead)
{
    int i = blockIdx.x * 256 + threadIdx.x;
    if (i < HH * DD / 4) {
        int row = i >> 6;
        int c4  = i & 63;
        int r = ghead[row];
        ((float4*)(g_A + (size_t)r * DD))[c4] =
            ((const float4*)(query + (size_t)r * DD))[c4];
    }
}

// ---------------------------------------------------------------------------
extern "C" void kernel_launch(void* const* d_in, const int* in_sizes, int n_in,
                              void* d_out, int out_size)
{
    const float* query = (const float*)d_in[0];
    const float* key   = (const float*)d_in[1];
    const float* value = (const float*)d_in[2];
    const int*   adj   = (const int*)d_in[3];
    const int*   cidx  = (const int*)d_in[4];
    const int*   gtail = (const int*)d_in[5];
    const int*   ghead = (const int*)d_in[6];
    const float* Wq = (const float*)d_in[7];
    const float* bq = (const float*)d_in[8];
    const float* Wk = (const float*)d_in[9];
    const float* bk = (const float*)d_in[10];
    const float* Wv = (const float*)d_in[11];
    const float* bv = (const float*)d_in[12];
    const float* Wo = (const float*)d_in[13];
    const float* bo = (const float*)d_in[14];
    const float* edge = (const float*)d_in[15];
    float* out = (float*)d_out;

    __half *pQh, *pKh, *pVth;
    float *pV, *pA;
    cudaGetSymbolAddress((void**)&pQh, g_Qh);
    cudaGetSymbolAddress((void**)&pKh, g_Kh);
    cudaGetSymbolAddress((void**)&pV,  g_V);
    cudaGetSymbolAddress((void**)&pVth, g_Vth);
    cudaGetSymbolAddress((void**)&pA,  g_A);

    const float SCALE_Q = 0.17677669529663687f * LOG2E;  // 32^-0.5 * log2(e)

    zero_A_kernel<<<(NTOT * DD / 4 + 255) / 256, 256>>>();

    dim3 gq(4, (TT + 63) / 64);
    gemm_kernel<<<gq, 256>>>(query, gtail, Wq, bq, nullptr, pQh, TT, SCALE_Q);
    dim3 gk(4, (HH + 63) / 64);
    gemm_kernel<<<gk, 256>>>(key,   ghead, Wk, bk, nullptr, pKh, HH, 1.0f);
    gemm_kernel<<<gk, 256>>>(value, ghead, Wv, bv, pV, nullptr, HH, 1.0f);

    transpose_v_kernel<<<dim3(HH / 32, DD / 32), 256>>>();

    copy_head_kernel<<<(HH * DD / 4 + 255) / 256, 256>>>(query, ghead);

    dim3 ga((TT + 31) / 32, 2);
    attn_mma_kernel<<<ga, 128>>>(adj, cidx, gtail, edge);

    dim3 go(4, (NTOT + 63) / 64);
    gemm_kernel<<<go, 256>>>(pA, nullptr, Wo, bo, out, nullptr, NTOT, 1.0f);
}

// round 6
// speedup vs baseline: 2.9527x; 1.1207x over previous
#include <cuda_runtime.h>
#include <cuda_fp16.h>
#include <cstdint>
#include <cstddef>

// Problem constants
#define NTOT 12000
#define TT   6000
#define HH   4000
#define DD   256
#define NH   8
#define HD   32
#define EV   64
#define LOG2E 1.4426950408889634f

typedef unsigned long long u64;
typedef unsigned int u32;

// Scratch (device globals -- no allocation allowed)
__device__ __half g_Qx[(size_t)NTOT * DD];  // fp16 copy of query
__device__ __half g_Kx[(size_t)NTOT * DD];  // fp16 copy of key
__device__ __half g_Vx[(size_t)NTOT * DD];  // fp16 copy of value
__device__ __half g_Wh[4 * DD * DD];        // fp16 Wq,Wk,Wv,Wo
__device__ __half g_Qh[(size_t)TT * DD];    // projected+scaled queries (log2 domain)
__device__ __half g_Kh[(size_t)HH * DD];    // projected keys
__device__ __half g_Vh[(size_t)HH * DD];    // projected values
__device__ __half g_Vth[(size_t)DD * HH];   // transposed values [dim][key]
__device__ __half g_Ah[(size_t)NTOT * DD];  // assembled attn_all (fp16)

// ---------- helpers ----------
__device__ __forceinline__ float ex2f(float x) {
    float r; asm("ex2.approx.ftz.f32 %0, %1;" : "=f"(r) : "f"(x)); return r;
}
__device__ __forceinline__ u32 packh2(float lo, float hi) {
    u32 r; asm("cvt.rn.f16x2.f32 %0, %1, %2;" : "=r"(r) : "f"(hi), "f"(lo)); return r;
}
__device__ __forceinline__ u32 smem_u32(const void* p) {
    u32 a; asm("{ .reg .u64 t; cvta.to.shared.u64 t, %1; cvt.u32.u64 %0, t; }" : "=r"(a) : "l"(p));
    return a;
}
__device__ __forceinline__ void cp16(void* dst, const void* src) {
    asm volatile("cp.async.cg.shared.global [%0], [%1], 16;"
                 :: "r"(smem_u32(dst)), "l"(src) : "memory");
}
#define CP_COMMIT() asm volatile("cp.async.commit_group;" ::: "memory")
#define CP_WAIT1()  asm volatile("cp.async.wait_group 1;" ::: "memory")
#define CP_WAIT0()  asm volatile("cp.async.wait_group 0;" ::: "memory")

// mma.sync m16n8k16 f16 x f16 -> f32
__device__ __forceinline__ void mma_f16(float* d, const u32* a, u32 b0, u32 b1) {
    asm volatile(
        "mma.sync.aligned.m16n8k16.row.col.f32.f16.f16.f32 "
        "{%0,%1,%2,%3}, {%4,%5,%6,%7}, {%8,%9}, {%0,%1,%2,%3};"
        : "+f"(d[0]), "+f"(d[1]), "+f"(d[2]), "+f"(d[3])
        : "r"(a[0]), "r"(a[1]), "r"(a[2]), "r"(a[3]), "r"(b0), "r"(b1));
}

// ---------------------------------------------------------------------------
// fp32 -> fp16 converts
// ---------------------------------------------------------------------------
__global__ void __launch_bounds__(256) cvt_x_kernel(
    const float* __restrict__ q, const float* __restrict__ k,
    const float* __restrict__ v)
{
    const float* src = (blockIdx.y == 0) ? q : (blockIdx.y == 1) ? k : v;
    __half* dst = (blockIdx.y == 0) ? g_Qx : (blockIdx.y == 1) ? g_Kx : g_Vx;
    int i = blockIdx.x * 256 + threadIdx.x;          // float4 index
    if (i < NTOT * DD / 4) {
        float4 f = ((const float4*)src)[i];
        uint2 o; o.x = packh2(f.x, f.y); o.y = packh2(f.z, f.w);
        ((uint2*)dst)[i] = o;
    }
}

__global__ void __launch_bounds__(256) cvt_w_kernel(
    const float* __restrict__ wq, const float* __restrict__ wk,
    const float* __restrict__ wv, const float* __restrict__ wo)
{
    const float* src = (blockIdx.y == 0) ? wq : (blockIdx.y == 1) ? wk
                     : (blockIdx.y == 2) ? wv : wo;
    __half* dst = g_Wh + (size_t)blockIdx.y * DD * DD;
    int i = blockIdx.x * 256 + threadIdx.x;
    if (i < DD * DD / 4) {
        float4 f = ((const float4*)src)[i];
        uint2 o; o.x = packh2(f.x, f.y); o.y = packh2(f.z, f.w);
        ((uint2*)dst)[i] = o;
    }
}

// ---------------------------------------------------------------------------
// fp16 mma GEMM: Y[m,:] = (X[src(m),:] @ W^T + bias) * scale
// Block 256 thr = 8 warps; tile 128(M) x 64(N); K chunks of 32, double-buffered.
// Warp tile 32x32: warp_m = w&3, warp_n = w>>2.
// ---------------------------------------------------------------------------
__global__ void __launch_bounds__(256, 3) gemm_h_kernel(
    const __half* __restrict__ Xh, const int* __restrict__ idx,
    const __half* __restrict__ Wh, const float* __restrict__ bias,
    float* __restrict__ Yf, __half* __restrict__ Yh, int M, float scale)
{
    __shared__ __align__(16) __half Ah[2][128][40];
    __shared__ __align__(16) __half Bh[2][64][40];

    const int tid = threadIdx.x;
    const int w = tid >> 5, lane = tid & 31;
    const int g = lane >> 2, tq = lane & 3;
    const int wm = (w & 3) * 32, wn = (w >> 2) * 32;
    const int m0 = blockIdx.y * 128, n0 = blockIdx.x * 64;

    // staging assignments (fixed per thread)
    const int ar = tid >> 2, aseg = tid & 3;         // A rows ar, ar+64
    int xr0 = m0 + ar;       if (xr0 >= M) xr0 = M - 1;
    int xr1 = m0 + ar + 64;  if (xr1 >= M) xr1 = M - 1;
    if (idx) { xr0 = idx[xr0]; xr1 = idx[xr1]; }
    const __half* xp0 = Xh + (size_t)xr0 * DD + aseg * 8;
    const __half* xp1 = Xh + (size_t)xr1 * DD + aseg * 8;
    const __half* wp  = Wh + (size_t)(n0 + ar) * DD + aseg * 8;  // ar<64 valid (n0+63<256)

    float C[2][4][4];
#pragma unroll
    for (int mt = 0; mt < 2; mt++)
#pragma unroll
        for (int nt = 0; nt < 4; nt++)
#pragma unroll
            for (int j = 0; j < 4; j++) C[mt][nt][j] = 0.f;

    // preload k-chunk 0
    cp16(&Ah[0][ar][aseg * 8],      xp0);
    cp16(&Ah[0][ar + 64][aseg * 8], xp1);
    if (ar < 64) cp16(&Bh[0][ar][aseg * 8], wp);
    CP_COMMIT();

    for (int kc = 0; kc < 8; kc++) {
        const int buf = kc & 1;
        if (kc + 1 < 8) {
            int ko = (kc + 1) * 32;
            cp16(&Ah[buf ^ 1][ar][aseg * 8],      xp0 + ko);
            cp16(&Ah[buf ^ 1][ar + 64][aseg * 8], xp1 + ko);
            if (ar < 64) cp16(&Bh[buf ^ 1][ar][aseg * 8], wp + ko);
            CP_COMMIT();
            CP_WAIT1();
        } else {
            CP_WAIT0();
        }
        __syncthreads();

#pragma unroll
        for (int kt = 0; kt < 2; kt++) {
            u32 A[2][4];
#pragma unroll
            for (int mt = 0; mt < 2; mt++) {
                const __half* ap = &Ah[buf][wm + mt * 16 + g][kt * 16 + 2 * tq];
                A[mt][0] = *(const u32*)ap;
                A[mt][1] = *(const u32*)(ap + 8 * 40);
                A[mt][2] = *(const u32*)(ap + 8);
                A[mt][3] = *(const u32*)(ap + 8 * 40 + 8);
            }
#pragma unroll
            for (int nt = 0; nt < 4; nt++) {
                const __half* bp = &Bh[buf][wn + nt * 8 + g][kt * 16 + 2 * tq];
                u32 b0 = *(const u32*)bp;
                u32 b1 = *(const u32*)(bp + 8);
                mma_f16(C[0][nt], A[0], b0, b1);
                mma_f16(C[1][nt], A[1], b0, b1);
            }
        }
        __syncthreads();
    }

    // epilogue
#pragma unroll
    for (int nt = 0; nt < 4; nt++) {
        int n = n0 + wn + nt * 8 + 2 * tq;
        float b0 = bias[n], b1 = bias[n + 1];
#pragma unroll
        for (int mt = 0; mt < 2; mt++) {
            int mA = m0 + wm + mt * 16 + g;
            int mB = mA + 8;
            float v0 = (C[mt][nt][0] + b0) * scale;
            float v1 = (C[mt][nt][1] + b1) * scale;
            float v2 = (C[mt][nt][2] + b0) * scale;
            float v3 = (C[mt][nt][3] + b1) * scale;
            if (Yh) {
                if (mA < M) *(u32*)(Yh + (size_t)mA * DD + n) = packh2(v0, v1);
                if (mB < M) *(u32*)(Yh + (size_t)mB * DD + n) = packh2(v2, v3);
            } else {
                if (mA < M) { float2 t = {v0, v1}; *(float2*)(Yf + (size_t)mA * DD + n) = t; }
                if (mB < M) { float2 t = {v2, v3}; *(float2*)(Yf + (size_t)mB * DD + n) = t; }
            }
        }
    }
}

// ---------------------------------------------------------------------------
// V transpose (fp16): g_Vh[4000][256] -> g_Vth[256][4000]
// ---------------------------------------------------------------------------
__global__ void __launch_bounds__(256) transpose_v_kernel()
{
    __shared__ __half t[32][34];
    int s0 = blockIdx.x * 32, d0 = blockIdx.y * 32;
    int x = threadIdx.x & 31, y = threadIdx.x >> 5;   // 32x8
#pragma unroll
    for (int i = 0; i < 32; i += 8)
        t[y + i][x] = g_Vh[(size_t)(s0 + y + i) * DD + d0 + x];
    __syncthreads();
#pragma unroll
    for (int i = 0; i < 32; i += 8)
        g_Vth[(size_t)(d0 + y + i) * HH + s0 + x] = t[x][y + i];
}

// ---------------------------------------------------------------------------
// zero + head-copy for g_Ah
// ---------------------------------------------------------------------------
__global__ void zero_Ah_kernel()
{
    int i = blockIdx.x * 256 + threadIdx.x;
    if (i < NTOT * DD * 2 / 16)
        ((uint4*)g_Ah)[i] = make_uint4(0u, 0u, 0u, 0u);
}

__global__ void copy_head_kernel(const int* __restrict__ ghead)
{
    int i = blockIdx.x * 256 + threadIdx.x;   // uint4 over head rows (32 per row)
    if (i < HH * 32) {
        int row = i >> 5, c4 = i & 31;
        int r = ghead[row];
        ((uint4*)(g_Ah + (size_t)r * DD))[c4] = ((const uint4*)(g_Qx + (size_t)r * DD))[c4];
    }
}

// ---------------------------------------------------------------------------
// mma.sync fp16 flash attention, merged heads.
// Block = 256 threads = 8 warps = 8 heads; 16 tails/block; grid 375.
// Chunk = 16 keys; 250 chunks, cp.async double-buffered.
// ---------------------------------------------------------------------------
#define NCH 250

struct SmemT {
    __half Ks [2][16][264];   // [buf][key][256 dims + 8 pad]  (528B rows)
    __half Vts[2][256][24];   // [buf][dim][16 keys + 8 pad]   (48B rows)
    int    adjS[2][16][20];   // [buf][tail][16 keys + 4 pad]  (80B rows)
    int    cidS[2][16][20];
    float  edge[NH][EV];      // edge bias table (log2-scaled)
};

__device__ __forceinline__ void stage_tiles(SmemT* s, int b, int it,
    const int* __restrict__ adj, const int* __restrict__ cidx,
    int tid, int t0)
{
    const int s0 = it * 16;
#pragma unroll
    for (int i = 0; i < 2; i++) {       // K tile: 16 rows x 512B = 512 cp16
        int e = tid + i * 256;
        int r = e >> 5, seg = e & 31;
        cp16(&s->Ks[b][r][seg * 8], g_Kh + ((size_t)(s0 + r) * DD + seg * 8));
    }
#pragma unroll
    for (int i = 0; i < 2; i++) {       // Vt tile: 256 rows x 32B = 512 cp16
        int e = tid + i * 256;
        int r = e >> 1, seg = e & 1;
        cp16(&s->Vts[b][r][seg * 8], g_Vth + ((size_t)r * HH + s0 + seg * 8));
    }
    if (tid < 128) {                    // adj/cid: 16 rows x 64B each
        int a = tid >> 6;               // 0 = adj, 1 = cid
        int t = tid & 63;
        int r = t >> 2, seg = t & 3;
        const int* src = (a ? cidx : adj) + (size_t)(t0 + r) * HH + s0 + seg * 4;
        int* dst = (a ? &s->cidS[b][r][seg * 4] : &s->adjS[b][r][seg * 4]);
        cp16(dst, src);
    }
}

__global__ void __launch_bounds__(256, 3) attn_mma_kernel(
    const int* __restrict__ adj, const int* __restrict__ cidx,
    const int* __restrict__ gtail, const float* __restrict__ edge_emb)
{
    __shared__ SmemT sm;

    const int tid = threadIdx.x;
    const int w   = tid >> 5;          // warp = head
    const int lane = tid & 31;
    const int g   = lane >> 2;
    const int tq  = lane & 3;
    const int t0  = blockIdx.x * 16;

    for (int i = tid; i < NH * EV; i += 256) {
        int ww = i >> 6, c = i & 63;
        sm.edge[ww][c] = edge_emb[c * NH + ww] * LOG2E;
    }

    // Q A-fragments (persist): Qa[ktile][4]; rows t0+g, t0+g+8 (exact, 6000=375*16)
    u32 Qa[2][4];
#pragma unroll
    for (int kt = 0; kt < 2; kt++) {
        const __half* q0 = g_Qh + (size_t)(t0 + g) * DD + w * HD + kt * 16 + 2 * tq;
        const __half* q1 = g_Qh + (size_t)(t0 + g + 8) * DD + w * HD + kt * 16 + 2 * tq;
        Qa[kt][0] = *(const u32*)q0;
        Qa[kt][1] = *(const u32*)q1;
        Qa[kt][2] = *(const u32*)(q0 + 8);
        Qa[kt][3] = *(const u32*)(q1 + 8);
    }

    float O[4][4];
#pragma unroll
    for (int n = 0; n < 4; n++)
#pragma unroll
        for (int j = 0; j < 4; j++) O[n][j] = 0.f;
    float l0 = 0.f, l1 = 0.f;

    stage_tiles(&sm, 0, 0, adj, cidx, tid, t0);
    CP_COMMIT();

    for (int it = 0; it < NCH; it++) {
        const int buf = it & 1;
        if (it + 1 < NCH) {
            stage_tiles(&sm, buf ^ 1, it + 1, adj, cidx, tid, t0);
            CP_COMMIT();
            CP_WAIT1();
        } else {
            CP_WAIT0();
        }
        __syncthreads();

        // ---- QK: S[nt] = Q . K^T  (16 keys = 2 n8 tiles) ----
        float S[2][4];
#pragma unroll
        for (int nt = 0; nt < 2; nt++)
#pragma unroll
            for (int j = 0; j < 4; j++) S[nt][j] = 0.f;

#pragma unroll
        for (int nt = 0; nt < 2; nt++) {
#pragma unroll
            for (int kt = 0; kt < 2; kt++) {
                const __half* kp = &sm.Ks[buf][nt * 8 + g][w * HD + kt * 16 + 2 * tq];
                u32 b0 = *(const u32*)kp;
                u32 b1 = *(const u32*)(kp + 8);
                mma_f16(S[nt], Qa[kt], b0, b1);
            }
        }

        // ---- softmax (fixed-reference, log2 domain) ----
        // Pa layout = {p(g,k0), p(g+8,k0), p(g,k8), p(g+8,k8)} == m16k16 A-frag order
        u32 Pa[4];
#pragma unroll
        for (int nt = 0; nt < 2; nt++) {
            int colb = nt * 8 + 2 * tq;
            int2 a0 = *(const int2*)&sm.adjS[buf][g][colb];
            int2 a1 = *(const int2*)&sm.adjS[buf][g + 8][colb];
            int2 c0 = *(const int2*)&sm.cidS[buf][g][colb];
            int2 c1 = *(const int2*)&sm.cidS[buf][g + 8][colb];
            float p00 = a0.x ? ex2f(S[nt][0] + sm.edge[w][c0.x]) : 0.f;
            float p01 = a0.y ? ex2f(S[nt][1] + sm.edge[w][c0.y]) : 0.f;
            float p10 = a1.x ? ex2f(S[nt][2] + sm.edge[w][c1.x]) : 0.f;
            float p11 = a1.y ? ex2f(S[nt][3] + sm.edge[w][c1.y]) : 0.f;
            l0 += p00 + p01;
            l1 += p10 + p11;
            Pa[nt * 2 + 0] = packh2(p00, p01);
            Pa[nt * 2 + 1] = packh2(p10, p11);
        }

        // ---- PV: O[nd] += P . V ----
#pragma unroll
        for (int nd = 0; nd < 4; nd++) {
            const __half* vp = &sm.Vts[buf][w * HD + nd * 8 + g][2 * tq];
            u32 b0 = *(const u32*)vp;
            u32 b1 = *(const u32*)(vp + 8);
            mma_f16(O[nd], Pa, b0, b1);
        }
        __syncthreads();
    }

    // quad-reduce l over tq lanes
    l0 += __shfl_xor_sync(0xffffffffu, l0, 1);
    l0 += __shfl_xor_sync(0xffffffffu, l0, 2);
    l1 += __shfl_xor_sync(0xffffffffu, l1, 1);
    l1 += __shfl_xor_sync(0xffffffffu, l1, 2);
    float inv0 = 1.0f / l0;
    float inv1 = 1.0f / l1;

    int r0 = gtail[t0 + g];
    int r1 = gtail[t0 + g + 8];
    __half* d0 = g_Ah + (size_t)r0 * DD + w * HD;
    __half* d1 = g_Ah + (size_t)r1 * DD + w * HD;
#pragma unroll
    for (int nd = 0; nd < 4; nd++) {
        *(u32*)(d0 + nd * 8 + 2 * tq) = packh2(O[nd][0] * inv0, O[nd][1] * inv0);
        *(u32*)(d1 + nd * 8 + 2 * tq) = packh2(O[nd][2] * inv1, O[nd][3] * inv1);
    }
}

// ---------------------------------------------------------------------------
extern "C" void kernel_launch(void* const* d_in, const int* in_sizes, int n_in,
                              void* d_out, int out_size)
{
    const float* query = (const float*)d_in[0];
    const float* key   = (const float*)d_in[1];
    const float* value = (const float*)d_in[2];
    const int*   adj   = (const int*)d_in[3];
    const int*   cidx  = (const int*)d_in[4];
    const int*   gtail = (const int*)d_in[5];
    const int*   ghead = (const int*)d_in[6];
    const float* Wq = (const float*)d_in[7];
    const float* bq = (const float*)d_in[8];
    const float* Wk = (const float*)d_in[9];
    const float* bk = (const float*)d_in[10];
    const float* Wv = (const float*)d_in[11];
    const float* bv = (const float*)d_in[12];
    const float* Wo = (const float*)d_in[13];
    const float* bo = (const float*)d_in[14];
    const float* edge = (const float*)d_in[15];
    float* out = (float*)d_out;

    __half *pQx, *pKx, *pVx, *pWh, *pQh, *pKh, *pVh, *pAh;
    cudaGetSymbolAddress((void**)&pQx, g_Qx);
    cudaGetSymbolAddress((void**)&pKx, g_Kx);
    cudaGetSymbolAddress((void**)&pVx, g_Vx);
    cudaGetSymbolAddress((void**)&pWh, g_Wh);
    cudaGetSymbolAddress((void**)&pQh, g_Qh);
    cudaGetSymbolAddress((void**)&pKh, g_Kh);
    cudaGetSymbolAddress((void**)&pVh, g_Vh);
    cudaGetSymbolAddress((void**)&pAh, g_Ah);

    const float SCALE_Q = 0.17677669529663687f * LOG2E;  // 32^-0.5 * log2(e)

    zero_Ah_kernel<<<(NTOT * DD * 2 / 16 + 255) / 256, 256>>>();
    cvt_x_kernel<<<dim3((NTOT * DD / 4 + 255) / 256, 3), 256>>>(query, key, value);
    cvt_w_kernel<<<dim3((DD * DD / 4 + 255) / 256, 4), 256>>>(Wq, Wk, Wv, Wo);

    // projections (fp16 mma)
    gemm_h_kernel<<<dim3(4, (TT + 127) / 128), 256>>>(
        pQx, gtail, pWh + 0 * DD * DD, bq, nullptr, pQh, TT, SCALE_Q);
    gemm_h_kernel<<<dim3(4, (HH + 127) / 128), 256>>>(
        pKx, ghead, pWh + 1 * DD * DD, bk, nullptr, pKh, HH, 1.0f);
    gemm_h_kernel<<<dim3(4, (HH + 127) / 128), 256>>>(
        pVx, ghead, pWh + 2 * DD * DD, bv, nullptr, pVh, HH, 1.0f);

    transpose_v_kernel<<<dim3(HH / 32, DD / 32), 256>>>();
    copy_head_kernel<<<(HH * 32 + 255) / 256, 256>>>(ghead);

    attn_mma_kernel<<<TT / 16, 256>>>(adj, cidx, gtail, edge);

    // output projection (f32 out)
    gemm_h_kernel<<<dim3(4, (NTOT + 127) / 128), 256>>>(
        pAh, nullptr, pWh + 3 * DD * DD, bo, out, nullptr, NTOT, 1.0f);
}

// round 7
// speedup vs baseline: 3.0498x; 1.0329x over previous
#include <cuda_runtime.h>
#include <cuda_fp16.h>
#include <cstdint>
#include <cstddef>

// Problem constants
#define NTOT 12000
#define TT   6000
#define HH   4000
#define DD   256
#define NH   8
#define HD   32
#define EV   64
#define LOG2E 1.4426950408889634f

typedef unsigned long long u64;
typedef unsigned int u32;
typedef unsigned short u16;
typedef unsigned char u8;

// Scratch (device globals -- no allocation allowed)
__device__ __half g_Qx[(size_t)NTOT * DD];   // fp16 query
__device__ __half g_Kx[(size_t)NTOT * DD];   // fp16 key
__device__ __half g_Vx[(size_t)NTOT * DD];   // fp16 value
__device__ __half g_Wh[4 * DD * DD];         // fp16 Wq,Wk,Wv,Wo
__device__ __half g_Qh[(size_t)TT * DD];     // projected+scaled queries (log2 domain)
__device__ __half g_Kh[(size_t)HH * DD];     // projected keys
__device__ __half g_Vh[(size_t)HH * DD];     // projected values
__device__ __half g_Vtt[(size_t)(HH / 16) * DD * 16];  // tiled V^T: [chunk][dim][16 keys]
__device__ u8     g_code[(size_t)TT * HH];   // packed mask/edge codes (0x80 = masked)
__device__ __half g_Ah[(size_t)NTOT * DD];   // assembled attn_all (fp16)

// ---------- helpers ----------
__device__ __forceinline__ float ex2f(float x) {
    float r; asm("ex2.approx.ftz.f32 %0, %1;" : "=f"(r) : "f"(x)); return r;
}
__device__ __forceinline__ u32 packh2(float lo, float hi) {
    u32 r; asm("cvt.rn.f16x2.f32 %0, %1, %2;" : "=r"(r) : "f"(hi), "f"(lo)); return r;
}
__device__ __forceinline__ u32 smem_u32(const void* p) {
    u32 a; asm("{ .reg .u64 t; cvta.to.shared.u64 t, %1; cvt.u32.u64 %0, t; }" : "=r"(a) : "l"(p));
    return a;
}
__device__ __forceinline__ void cp16(void* dst, const void* src) {
    asm volatile("cp.async.cg.shared.global [%0], [%1], 16;"
                 :: "r"(smem_u32(dst)), "l"(src) : "memory");
}
#define CP_COMMIT() asm volatile("cp.async.commit_group;" ::: "memory")
#define CP_WAIT1()  asm volatile("cp.async.wait_group 1;" ::: "memory")
#define CP_WAIT0()  asm volatile("cp.async.wait_group 0;" ::: "memory")

// mma.sync m16n8k16 f16 x f16 -> f32
__device__ __forceinline__ void mma_f16(float* d, const u32* a, u32 b0, u32 b1) {
    asm volatile(
        "mma.sync.aligned.m16n8k16.row.col.f32.f16.f16.f32 "
        "{%0,%1,%2,%3}, {%4,%5,%6,%7}, {%8,%9}, {%0,%1,%2,%3};"
        : "+f"(d[0]), "+f"(d[1]), "+f"(d[2]), "+f"(d[3])
        : "r"(a[0]), "r"(a[1]), "r"(a[2]), "r"(a[3]), "r"(b0), "r"(b1));
}

// ---------------------------------------------------------------------------
// Fused prep: fp16 converts (x, W), code packing, g_Ah zeroing.
// grid (3000, 9). y=0..2 cvt q/k/v; y=3..6 cvt W; y=7 pack codes; y=8 zero.
// ---------------------------------------------------------------------------
__global__ void __launch_bounds__(256) prep_kernel(
    const float* __restrict__ q, const float* __restrict__ k,
    const float* __restrict__ v,
    const float* __restrict__ wq, const float* __restrict__ wk,
    const float* __restrict__ wv, const float* __restrict__ wo,
    const int* __restrict__ adj, const int* __restrict__ cidx)
{
    const int y = blockIdx.y;
    const int i = blockIdx.x * 256 + threadIdx.x;

    if (y < 3) {                                  // x converts (float4 granules)
        if (i < NTOT * DD / 4) {
            const float* src = (y == 0) ? q : (y == 1) ? k : v;
            __half* dst = (y == 0) ? g_Qx : (y == 1) ? g_Kx : g_Vx;
            float4 f = ((const float4*)src)[i];
            uint2 o; o.x = packh2(f.x, f.y); o.y = packh2(f.z, f.w);
            ((uint2*)dst)[i] = o;
        }
    } else if (y < 7) {                           // W converts
        if (i < DD * DD / 4) {
            int wsel = y - 3;
            const float* src = (wsel == 0) ? wq : (wsel == 1) ? wk
                             : (wsel == 2) ? wv : wo;
            __half* dst = g_Wh + (size_t)wsel * DD * DD;
            float4 f = ((const float4*)src)[i];
            uint2 o; o.x = packh2(f.x, f.y); o.y = packh2(f.z, f.w);
            ((uint2*)dst)[i] = o;
        }
    } else if (y == 7) {                          // pack codes, 32 entries/thread
        if (i < TT * HH / 32) {
            const int4* ap = (const int4*)adj  + (size_t)i * 8;
            const int4* cp = (const int4*)cidx + (size_t)i * 8;
            u32 ob[8];
#pragma unroll
            for (int j = 0; j < 8; j++) {
                int4 a = ap[j]; int4 c = cp[j];
                u32 b0 = a.x ? ((u32)c.x & 63u) : 0x80u;
                u32 b1 = a.y ? ((u32)c.y & 63u) : 0x80u;
                u32 b2 = a.z ? ((u32)c.z & 63u) : 0x80u;
                u32 b3 = a.w ? ((u32)c.w & 63u) : 0x80u;
                ob[j] = b0 | (b1 << 8) | (b2 << 16) | (b3 << 24);
            }
            uint4* dst = (uint4*)(g_code + (size_t)i * 32);
            dst[0] = make_uint4(ob[0], ob[1], ob[2], ob[3]);
            dst[1] = make_uint4(ob[4], ob[5], ob[6], ob[7]);
        }
    } else {                                      // zero g_Ah (uint4 granules)
        if (i < NTOT * DD * 2 / 16)
            ((uint4*)g_Ah)[i] = make_uint4(0u, 0u, 0u, 0u);
    }
}

// ---------------------------------------------------------------------------
// fp16 mma GEMM: Y[m,:] = (X[src(m),:] @ W^T + bias) * scale
// Block 256 thr = 8 warps; tile 128(M) x 64(N); K chunks of 32, double-buffered.
// ---------------------------------------------------------------------------
__global__ void __launch_bounds__(256, 3) gemm_h_kernel(
    const __half* __restrict__ Xh, const int* __restrict__ idx,
    const __half* __restrict__ Wh, const float* __restrict__ bias,
    float* __restrict__ Yf, __half* __restrict__ Yh, int M, float scale)
{
    __shared__ __align__(16) __half Ah[2][128][40];
    __shared__ __align__(16) __half Bh[2][64][40];

    const int tid = threadIdx.x;
    const int w = tid >> 5, lane = tid & 31;
    const int g = lane >> 2, tq = lane & 3;
    const int wm = (w & 3) * 32, wn = (w >> 2) * 32;
    const int m0 = blockIdx.y * 128, n0 = blockIdx.x * 64;

    const int ar = tid >> 2, aseg = tid & 3;
    int xr0 = m0 + ar;       if (xr0 >= M) xr0 = M - 1;
    int xr1 = m0 + ar + 64;  if (xr1 >= M) xr1 = M - 1;
    if (idx) { xr0 = idx[xr0]; xr1 = idx[xr1]; }
    const __half* xp0 = Xh + (size_t)xr0 * DD + aseg * 8;
    const __half* xp1 = Xh + (size_t)xr1 * DD + aseg * 8;
    const __half* wp  = Wh + (size_t)(n0 + ar) * DD + aseg * 8;

    float C[2][4][4];
#pragma unroll
    for (int mt = 0; mt < 2; mt++)
#pragma unroll
        for (int nt = 0; nt < 4; nt++)
#pragma unroll
            for (int j = 0; j < 4; j++) C[mt][nt][j] = 0.f;

    cp16(&Ah[0][ar][aseg * 8],      xp0);
    cp16(&Ah[0][ar + 64][aseg * 8], xp1);
    if (ar < 64) cp16(&Bh[0][ar][aseg * 8], wp);
    CP_COMMIT();

    for (int kc = 0; kc < 8; kc++) {
        const int buf = kc & 1;
        if (kc + 1 < 8) {
            int ko = (kc + 1) * 32;
            cp16(&Ah[buf ^ 1][ar][aseg * 8],      xp0 + ko);
            cp16(&Ah[buf ^ 1][ar + 64][aseg * 8], xp1 + ko);
            if (ar < 64) cp16(&Bh[buf ^ 1][ar][aseg * 8], wp + ko);
            CP_COMMIT();
            CP_WAIT1();
        } else {
            CP_WAIT0();
        }
        __syncthreads();

#pragma unroll
        for (int kt = 0; kt < 2; kt++) {
            u32 A[2][4];
#pragma unroll
            for (int mt = 0; mt < 2; mt++) {
                const __half* ap = &Ah[buf][wm + mt * 16 + g][kt * 16 + 2 * tq];
                A[mt][0] = *(const u32*)ap;
                A[mt][1] = *(const u32*)(ap + 8 * 40);
                A[mt][2] = *(const u32*)(ap + 8);
                A[mt][3] = *(const u32*)(ap + 8 * 40 + 8);
            }
#pragma unroll
            for (int nt = 0; nt < 4; nt++) {
                const __half* bp = &Bh[buf][wn + nt * 8 + g][kt * 16 + 2 * tq];
                u32 b0 = *(const u32*)bp;
                u32 b1 = *(const u32*)(bp + 8);
                mma_f16(C[0][nt], A[0], b0, b1);
                mma_f16(C[1][nt], A[1], b0, b1);
            }
        }
        __syncthreads();
    }

#pragma unroll
    for (int nt = 0; nt < 4; nt++) {
        int n = n0 + wn + nt * 8 + 2 * tq;
        float b0 = bias[n], b1 = bias[n + 1];
#pragma unroll
        for (int mt = 0; mt < 2; mt++) {
            int mA = m0 + wm + mt * 16 + g;
            int mB = mA + 8;
            float v0 = (C[mt][nt][0] + b0) * scale;
            float v1 = (C[mt][nt][1] + b1) * scale;
            float v2 = (C[mt][nt][2] + b0) * scale;
            float v3 = (C[mt][nt][3] + b1) * scale;
            if (Yh) {
                if (mA < M) *(u32*)(Yh + (size_t)mA * DD + n) = packh2(v0, v1);
                if (mB < M) *(u32*)(Yh + (size_t)mB * DD + n) = packh2(v2, v3);
            } else {
                if (mA < M) { float2 t = {v0, v1}; *(float2*)(Yf + (size_t)mA * DD + n) = t; }
                if (mB < M) { float2 t = {v2, v3}; *(float2*)(Yf + (size_t)mB * DD + n) = t; }
            }
        }
    }
}

// ---------------------------------------------------------------------------
// V transpose to tiled layout: g_Vh[4000][256] -> g_Vtt[s/16][256][s%16]
// ---------------------------------------------------------------------------
__global__ void __launch_bounds__(256) transpose_v_kernel()
{
    __shared__ __half t[32][34];
    int s0 = blockIdx.x * 32, d0 = blockIdx.y * 32;
    int x = threadIdx.x & 31, y = threadIdx.x >> 5;   // 32x8
#pragma unroll
    for (int i = 0; i < 32; i += 8)
        t[y + i][x] = g_Vh[(size_t)(s0 + y + i) * DD + d0 + x];
    __syncthreads();
#pragma unroll
    for (int i = 0; i < 32; i += 8) {
        int s = s0 + x, d = d0 + y + i;
        g_Vtt[(size_t)(s >> 4) * (DD * 16) + d * 16 + (s & 15)] = t[x][y + i];
    }
}

// ---------------------------------------------------------------------------
// copy head rows into g_Ah
// ---------------------------------------------------------------------------
__global__ void copy_head_kernel(const int* __restrict__ ghead)
{
    int i = blockIdx.x * 256 + threadIdx.x;   // uint4 over head rows (32 per row)
    if (i < HH * 32) {
        int row = i >> 5, c4 = i & 31;
        int r = ghead[row];
        ((uint4*)(g_Ah + (size_t)r * DD))[c4] = ((const uint4*)(g_Qx + (size_t)r * DD))[c4];
    }
}

// ---------------------------------------------------------------------------
// mma.sync fp16 flash attention, merged heads + packed codes + tiled Vt.
// Block = 256 threads = 8 warps = 8 heads; 16 tails/block; grid 375.
// Chunk = 16 keys; 250 chunks, cp.async double-buffered.
// ---------------------------------------------------------------------------
#define NCH (HH / 16)

struct SmemT {
    __half Ks [2][16][264];   // [buf][key][256 dims + 8 pad]  (528B rows)
    __half Vtt[2][256][24];   // [buf][dim][16 keys + 8 pad]   (48B rows)
    u8     codeS[2][16][48];  // [buf][tail][16 codes + 32 pad] (48B rows, 16B-aligned)
    float  edge[NH][EV];      // edge bias table (log2-scaled)
};

__device__ __forceinline__ void stage_tiles(SmemT* s, int b, int it, int tid, int t0)
{
    const int s0 = it * 16;
#pragma unroll
    for (int i = 0; i < 2; i++) {       // K tile: 16 rows x 512B = 512 cp16
        int e = tid + i * 256;
        int r = e >> 5, seg = e & 31;
        cp16(&s->Ks[b][r][seg * 8], g_Kh + ((size_t)(s0 + r) * DD + seg * 8));
    }
#pragma unroll
    for (int i = 0; i < 2; i++) {       // Vt tile: contiguous 8KB in g_Vtt
        int e = tid + i * 256;
        int r = e >> 1, seg = e & 1;
        cp16(&s->Vtt[b][r][seg * 8], g_Vtt + ((size_t)it * (DD * 16) + r * 16 + seg * 8));
    }
    if (tid < 16)                       // codes: 16 tails x 16B
        cp16(&s->codeS[b][tid][0], g_code + (size_t)(t0 + tid) * HH + s0);
}

__global__ void __launch_bounds__(256, 3) attn_mma_kernel(
    const int* __restrict__ gtail, const float* __restrict__ edge_emb)
{
    __shared__ SmemT sm;

    const int tid = threadIdx.x;
    const int w   = tid >> 5;          // warp = head
    const int lane = tid & 31;
    const int g   = lane >> 2;
    const int tq  = lane & 3;
    const int t0  = blockIdx.x * 16;

    for (int i = tid; i < NH * EV; i += 256) {
        int ww = i >> 6, c = i & 63;
        sm.edge[ww][c] = edge_emb[c * NH + ww] * LOG2E;
    }

    // Q A-fragments (persist): rows t0+g, t0+g+8 (exact: 6000 = 375*16)
    u32 Qa[2][4];
#pragma unroll
    for (int kt = 0; kt < 2; kt++) {
        const __half* q0 = g_Qh + (size_t)(t0 + g) * DD + w * HD + kt * 16 + 2 * tq;
        const __half* q1 = g_Qh + (size_t)(t0 + g + 8) * DD + w * HD + kt * 16 + 2 * tq;
        Qa[kt][0] = *(const u32*)q0;
        Qa[kt][1] = *(const u32*)q1;
        Qa[kt][2] = *(const u32*)(q0 + 8);
        Qa[kt][3] = *(const u32*)(q1 + 8);
    }

    float O[4][4];
#pragma unroll
    for (int n = 0; n < 4; n++)
#pragma unroll
        for (int j = 0; j < 4; j++) O[n][j] = 0.f;
    float l0 = 0.f, l1 = 0.f;

    stage_tiles(&sm, 0, 0, tid, t0);
    CP_COMMIT();

    for (int it = 0; it < NCH; it++) {
        const int buf = it & 1;
        if (it + 1 < NCH) {
            stage_tiles(&sm, buf ^ 1, it + 1, tid, t0);
            CP_COMMIT();
            CP_WAIT1();
        } else {
            CP_WAIT0();
        }
        __syncthreads();

        // ---- QK: S[nt] = Q . K^T ----
        float S[2][4];
#pragma unroll
        for (int nt = 0; nt < 2; nt++)
#pragma unroll
            for (int j = 0; j < 4; j++) S[nt][j] = 0.f;

#pragma unroll
        for (int nt = 0; nt < 2; nt++) {
#pragma unroll
            for (int kt = 0; kt < 2; kt++) {
                const __half* kp = &sm.Ks[buf][nt * 8 + g][w * HD + kt * 16 + 2 * tq];
                u32 b0 = *(const u32*)kp;
                u32 b1 = *(const u32*)(kp + 8);
                mma_f16(S[nt], Qa[kt], b0, b1);
            }
        }

        // ---- softmax (fixed-reference, log2 domain), codes from u8 table ----
        u32 Pa[4];
#pragma unroll
        for (int nt = 0; nt < 2; nt++) {
            u32 wA = *(const u16*)&sm.codeS[buf][g][nt * 8 + 2 * tq];
            u32 wB = *(const u16*)&sm.codeS[buf][g + 8][nt * 8 + 2 * tq];
            u32 cA0 = wA & 0xFFu, cA1 = wA >> 8;
            u32 cB0 = wB & 0xFFu, cB1 = wB >> 8;
            float p00 = (cA0 & 0x80u) ? 0.f : ex2f(S[nt][0] + sm.edge[w][cA0]);
            float p01 = (cA1 & 0x80u) ? 0.f : ex2f(S[nt][1] + sm.edge[w][cA1 & 63u]);
            float p10 = (cB0 & 0x80u) ? 0.f : ex2f(S[nt][2] + sm.edge[w][cB0]);
            float p11 = (cB1 & 0x80u) ? 0.f : ex2f(S[nt][3] + sm.edge[w][cB1 & 63u]);
            l0 += p00 + p01;
            l1 += p10 + p11;
            Pa[nt * 2 + 0] = packh2(p00, p01);
            Pa[nt * 2 + 1] = packh2(p10, p11);
        }

        // ---- PV: O[nd] += P . V ----
#pragma unroll
        for (int nd = 0; nd < 4; nd++) {
            const __half* vp = &sm.Vtt[buf][w * HD + nd * 8 + g][2 * tq];
            u32 b0 = *(const u32*)vp;
            u32 b1 = *(const u32*)(vp + 8);
            mma_f16(O[nd], Pa, b0, b1);
        }
        __syncthreads();
    }

    // quad-reduce l over tq lanes
    l0 += __shfl_xor_sync(0xffffffffu, l0, 1);
    l0 += __shfl_xor_sync(0xffffffffu, l0, 2);
    l1 += __shfl_xor_sync(0xffffffffu, l1, 1);
    l1 += __shfl_xor_sync(0xffffffffu, l1, 2);
    float inv0 = 1.0f / l0;
    float inv1 = 1.0f / l1;

    int r0 = gtail[t0 + g];
    int r1 = gtail[t0 + g + 8];
    __half* d0 = g_Ah + (size_t)r0 * DD + w * HD;
    __half* d1 = g_Ah + (size_t)r1 * DD + w * HD;
#pragma unroll
    for (int nd = 0; nd < 4; nd++) {
        *(u32*)(d0 + nd * 8 + 2 * tq) = packh2(O[nd][0] * inv0, O[nd][1] * inv0);
        *(u32*)(d1 + nd * 8 + 2 * tq) = packh2(O[nd][2] * inv1, O[nd][3] * inv1);
    }
}

// ---------------------------------------------------------------------------
extern "C" void kernel_launch(void* const* d_in, const int* in_sizes, int n_in,
                              void* d_out, int out_size)
{
    const float* query = (const float*)d_in[0];
    const float* key   = (const float*)d_in[1];
    const float* value = (const float*)d_in[2];
    const int*   adj   = (const int*)d_in[3];
    const int*   cidx  = (const int*)d_in[4];
    const int*   gtail = (const int*)d_in[5];
    const int*   ghead = (const int*)d_in[6];
    const float* Wq = (const float*)d_in[7];
    const float* bq = (const float*)d_in[8];
    const float* Wk = (const float*)d_in[9];
    const float* bk = (const float*)d_in[10];
    const float* Wv = (const float*)d_in[11];
    const float* bv = (const float*)d_in[12];
    const float* Wo = (const float*)d_in[13];
    const float* bo = (const float*)d_in[14];
    const float* edge = (const float*)d_in[15];
    float* out = (float*)d_out;

    __half *pQx, *pKx, *pVx, *pWh, *pQh, *pKh, *pVh, *pAh;
    cudaGetSymbolAddress((void**)&pQx, g_Qx);
    cudaGetSymbolAddress((void**)&pKx, g_Kx);
    cudaGetSymbolAddress((void**)&pVx, g_Vx);
    cudaGetSymbolAddress((void**)&pWh, g_Wh);
    cudaGetSymbolAddress((void**)&pQh, g_Qh);
    cudaGetSymbolAddress((void**)&pKh, g_Kh);
    cudaGetSymbolAddress((void**)&pVh, g_Vh);
    cudaGetSymbolAddress((void**)&pAh, g_Ah);

    const float SCALE_Q = 0.17677669529663687f * LOG2E;  // 32^-0.5 * log2(e)

    // 1: fused prep (converts + code pack + zero)
    prep_kernel<<<dim3(3000, 9), 256>>>(query, key, value, Wq, Wk, Wv, Wo, adj, cidx);

    // 2-4: projections (fp16 mma)
    gemm_h_kernel<<<dim3(4, (TT + 127) / 128), 256>>>(
        pQx, gtail, pWh + 0 * DD * DD, bq, nullptr, pQh, TT, SCALE_Q);
    gemm_h_kernel<<<dim3(4, (HH + 127) / 128), 256>>>(
        pKx, ghead, pWh + 1 * DD * DD, bk, nullptr, pKh, HH, 1.0f);
    gemm_h_kernel<<<dim3(4, (HH + 127) / 128), 256>>>(
        pVx, ghead, pWh + 2 * DD * DD, bv, nullptr, pVh, HH, 1.0f);

    // 5: V transpose to tiled layout
    transpose_v_kernel<<<dim3(HH / 32, DD / 32), 256>>>();

    // 6: attention (ncu -s 5 -c 1 captures this launch)
    attn_mma_kernel<<<TT / 16, 256>>>(gtail, edge);

    // 7: head-row copy
    copy_head_kernel<<<(HH * 32 + 255) / 256, 256>>>(ghead);

    // 8: output projection (f32 out)
    gemm_h_kernel<<<dim3(4, (NTOT + 127) / 128), 256>>>(
        pAh, nullptr, pWh + 3 * DD * DD, bo, out, nullptr, NTOT, 1.0f);
}